// round 15
// baseline (speedup 1.0000x reference)
#include <cuda_runtime.h>
#include <cuda_fp16.h>
#include <math.h>
#include <stdint.h>

#define T_TOK 16384
#define HDIM  4096
#define NEXP  256
#define TOPK  8
#define TOPK_GRP 4

#define BM 128
#define BN 128
#define KC 64
#define NSM 148
#define THREADS 512

// refine (full 3-term) stage layout
#define AH_OFF 0
#define AL_OFF 16384
#define BH_OFF 32768
#define BL_OFF 49152
#define STAGE_BYTES 65536
#define SM_TOTAL (2 * STAGE_BYTES)

// phase-1 (hi-only, 128x256 tile, 2 chunks per stage)
#define P_A0 0
#define P_A1 16384
#define P_B0 32768
#define P_B1 65536
#define P_STAGE 98304
#define P_SM_TOTAL (2 * P_STAGE)
#define NCOLS_HI (128 * 64)

// margin thresholds (score space) — validated R10-R14
#define TH_EXP 8e-4f
#define TH_GRP 1.6e-3f

#define KSPLIT 4
#define NCH_Q  (HDIM / KC / KSPLIT)

__device__ float g_part0[(size_t)T_TOK * NEXP];
__device__ float g_part1[(size_t)T_TOK * NEXP];
__device__ float g_part2[(size_t)T_TOK * NEXP];
__device__ float g_rbuf[KSPLIT][(size_t)T_TOK * NEXP];
__device__ int   g_cnt;
__device__ int   g_list[T_TOK];
__device__ __align__(16) __half g_wh[(size_t)NEXP * HDIM];

// ---------------- helpers ----------------
__device__ __forceinline__ uint32_t smem_u32(const void* p) {
    uint32_t a;
    asm("{ .reg .u64 t; cvta.to.shared.u64 t, %1; cvt.u32.u64 %0, t; }" : "=r"(a) : "l"(p));
    return a;
}
__device__ __forceinline__ void sts128(uint32_t addr, uint32_t x, uint32_t y,
                                       uint32_t z, uint32_t w) {
    asm volatile("st.shared.v4.b32 [%0], {%1, %2, %3, %4};"
                 :: "r"(addr), "r"(x), "r"(y), "r"(z), "r"(w) : "memory");
}
__device__ __forceinline__ void ldsm4(uint32_t* r, uint32_t addr) {
    asm volatile("ldmatrix.sync.aligned.m8n8.x4.shared.b16 {%0, %1, %2, %3}, [%4];"
                 : "=r"(r[0]), "=r"(r[1]), "=r"(r[2]), "=r"(r[3]) : "r"(addr));
}
__device__ __forceinline__ void mma_f16(float* c, const uint32_t* a,
                                        uint32_t b0, uint32_t b1) {
    asm volatile(
        "mma.sync.aligned.m16n8k16.row.col.f32.f16.f16.f32 "
        "{%0, %1, %2, %3}, {%4, %5, %6, %7}, {%8, %9}, {%0, %1, %2, %3};"
        : "+f"(c[0]), "+f"(c[1]), "+f"(c[2]), "+f"(c[3])
        : "r"(a[0]), "r"(a[1]), "r"(a[2]), "r"(a[3]), "r"(b0), "r"(b1));
}
__device__ __forceinline__ void split2(float a, float b, uint32_t& h, uint32_t& l) {
    __half ha = __float2half_rn(a), hb = __float2half_rn(b);
    float ra = a - __half2float(ha);
    float rb = b - __half2float(hb);
    __half2 ph = __halves2half2(ha, hb);
    __half2 pl = __halves2half2(__float2half_rn(ra), __float2half_rn(rb));
    h = *reinterpret_cast<uint32_t*>(&ph);
    l = *reinterpret_cast<uint32_t*>(&pl);
}
__device__ __forceinline__ uint32_t packh2(float a, float b) {
    __half2 p = __floats2half2_rn(a, b);
    return *reinterpret_cast<uint32_t*>(&p);
}
__device__ __forceinline__ void cvt_sts8(uint32_t addr_hi, uint32_t addr_lo,
                                         float4 v0, float4 v1) {
    uint32_t h[4], l[4];
    split2(v0.x, v0.y, h[0], l[0]);
    split2(v0.z, v0.w, h[1], l[1]);
    split2(v1.x, v1.y, h[2], l[2]);
    split2(v1.z, v1.w, h[3], l[3]);
    sts128(addr_hi, h[0], h[1], h[2], h[3]);
    sts128(addr_lo, l[0], l[1], l[2], l[3]);
}
__device__ __forceinline__ void cvt_sts8_hi(uint32_t addr, float4 v0, float4 v1) {
    sts128(addr, packh2(v0.x, v0.y), packh2(v0.z, v0.w),
           packh2(v1.x, v1.y), packh2(v1.z, v1.w));
}

// W-hi preconvert; also resets g_cnt (merged reset kernel)
__global__ __launch_bounds__(256) void w_convert(const float* __restrict__ W) {
    if (blockIdx.x == 0 && threadIdx.x == 0) g_cnt = 0;
    const int idx = blockIdx.x * 256 + threadIdx.x;
    float4 v = ((const float4*)W)[idx];
    v.x *= 64.f; v.y *= 64.f; v.z *= 64.f; v.w *= 64.f;
    ((uint2*)g_wh)[idx] = make_uint2(packh2(v.x, v.y), packh2(v.z, v.w));
}

// full 3-term k16 step (R8-verified)
#define K16_STEP(K16)                                                          \
    do {                                                                       \
        uint32_t ah[2][4], al[2][4], bh[2][4], bl[2][4];                       \
        const uint32_t asg = (uint32_t)((((K16) * 2 + jk) ^ axr) << 4);        \
        const uint32_t bsg = (uint32_t)((((K16) * 2 + jr) ^ bxr) << 4);        \
        _Pragma("unroll")                                                      \
        for (int mi = 0; mi < 2; mi++) {                                       \
            const uint32_t ra = abase + (uint32_t)(mi * 2048) + asg;           \
            ldsm4(ah[mi], st + AH_OFF + ra);                                   \
            ldsm4(al[mi], st + AL_OFF + ra);                                   \
        }                                                                      \
        _Pragma("unroll")                                                      \
        for (int q = 0; q < 2; q++) {                                          \
            const uint32_t rb = bbase + (uint32_t)(q * 2048) + bsg;            \
            ldsm4(bh[q], st + BH_OFF + rb);                                    \
            ldsm4(bl[q], st + BL_OFF + rb);                                    \
        }                                                                      \
        _Pragma("unroll")                                                      \
        for (int mi = 0; mi < 2; mi++)                                         \
            _Pragma("unroll")                                                  \
            for (int nj = 0; nj < 4; nj++) {                                   \
                const int q = nj >> 1, s2 = (nj & 1) * 2;                      \
                mma_f16(bacc[mi][nj], ah[mi], bh[q][s2], bh[q][s2 + 1]);       \
            }                                                                  \
        _Pragma("unroll")                                                      \
        for (int mi = 0; mi < 2; mi++)                                         \
            _Pragma("unroll")                                                  \
            for (int nj = 0; nj < 4; nj++) {                                   \
                const int q = nj >> 1, s2 = (nj & 1) * 2;                      \
                mma_f16(bacc[mi][nj], ah[mi], bl[q][s2], bl[q][s2 + 1]);       \
            }                                                                  \
        _Pragma("unroll")                                                      \
        for (int mi = 0; mi < 2; mi++)                                         \
            _Pragma("unroll")                                                  \
            for (int nj = 0; nj < 4; nj++) {                                   \
                const int q = nj >> 1, s2 = (nj & 1) * 2;                      \
                mma_f16(bacc[mi][nj], al[mi], bh[q][s2], bh[q][s2 + 1]);       \
            }                                                                  \
    } while (0)

// hi-only k16 step, warp tile 32x64: 6 LDSM -> 16 MMAs on (stA, stB)
#define K16_STEP_HI(K16)                                                       \
    do {                                                                       \
        uint32_t ah[2][4], bh[4][4];                                           \
        const uint32_t asg = (uint32_t)((((K16) * 2 + jk) ^ axr) << 4);        \
        const uint32_t bsg = (uint32_t)((((K16) * 2 + jr) ^ bxr) << 4);        \
        _Pragma("unroll")                                                      \
        for (int mi = 0; mi < 2; mi++)                                         \
            ldsm4(ah[mi], stA + abase + (uint32_t)(mi * 2048) + asg);          \
        _Pragma("unroll")                                                      \
        for (int p = 0; p < 4; p++)                                            \
            ldsm4(bh[p], stB + bbase + (uint32_t)(p * 2048) + bsg);            \
        _Pragma("unroll")                                                      \
        for (int mi = 0; mi < 2; mi++)                                         \
            _Pragma("unroll")                                                  \
            for (int nj = 0; nj < 8; nj++) {                                   \
                const int p = nj >> 1, s2 = (nj & 1) * 2;                      \
                mma_f16(macc[mi][nj], ah[mi], bh[p][s2], bh[p][s2 + 1]);       \
            }                                                                  \
    } while (0)

// ---------------------------------------------------------------------------
// phase-1 segment: hi*hi only, CTA tile 128x256, pair-scheduled producer
// ---------------------------------------------------------------------------
__device__ __forceinline__ void run_segment_hi(
    const float* __restrict__ A,
    float* __restrict__ dst, int m0, int lc0, int nch,
    uint32_t sb, int tid, int lane, int wid)
{
    __syncthreads();

    const int wm = wid & 3;
    const int wn = wid >> 2;

    // A producer: row = tid>>2 (0..127), 16-float seg = tid&3
    const int parow = tid >> 2;
    const int paseg = tid & 3;
    const float* pa = A + (size_t)(m0 + parow) * HDIM + lc0 * KC + paseg * 16;
    uint32_t a_sts[2];
#pragma unroll
    for (int i = 0; i < 2; i++) {
        int g = paseg * 2 + i;
        a_sts[i] = (uint32_t)(parow * 128 + (((g ^ (parow & 7)) & 7) << 4));
    }
    // B producer: row = tid>>1 (0..255), 64B half = tid&1
    const int pbrow = tid >> 1;
    const int pbseg = tid & 1;
    const __half* pb = g_wh + (size_t)pbrow * HDIM + lc0 * KC + pbseg * 32;
    uint32_t b_sts[4];
#pragma unroll
    for (int i = 0; i < 4; i++) {
        int g = pbseg * 4 + i;
        b_sts[i] = (uint32_t)(pbrow * 128 + (((g ^ (pbrow & 7)) & 7) << 4));
    }

    const int r  = lane & 7;
    const int j  = lane >> 3;
    const int jr = j & 1;
    const int jk = j >> 1;
    const int arow = wm * 32 + r + jr * 8;
    const int brow = wn * 64 + r + jk * 8;
    const uint32_t axr = (uint32_t)(arow & 7);
    const uint32_t bxr = (uint32_t)(brow & 7);
    const uint32_t abase = (uint32_t)(arow * 128);
    const uint32_t bbase = (uint32_t)(brow * 128);

    float macc[2][8][4];
#pragma unroll
    for (int mi = 0; mi < 2; mi++)
#pragma unroll
        for (int nj = 0; nj < 8; nj++)
#pragma unroll
            for (int q = 0; q < 4; q++) macc[mi][nj][q] = 0.0f;

    // prologue: chunks 0 (and 1) -> stage 0 subs 0/1
    {
        float4 a0 = *(const float4*)(pa + 0), a1 = *(const float4*)(pa + 4);
        float4 a2 = *(const float4*)(pa + 8), a3 = *(const float4*)(pa + 12);
        cvt_sts8_hi(sb + P_A0 + a_sts[0], a0, a1);
        cvt_sts8_hi(sb + P_A0 + a_sts[1], a2, a3);
#pragma unroll
        for (int i = 0; i < 4; i++) {
            uint4 h = *(const uint4*)(pb + i * 8);
            sts128(sb + P_B0 + b_sts[i], h.x, h.y, h.z, h.w);
        }
        if (nch > 1) {
            const float* qa = pa + KC;
            const __half* qb = pb + KC;
            a0 = *(const float4*)(qa + 0); a1 = *(const float4*)(qa + 4);
            a2 = *(const float4*)(qa + 8); a3 = *(const float4*)(qa + 12);
            cvt_sts8_hi(sb + P_A1 + a_sts[0], a0, a1);
            cvt_sts8_hi(sb + P_A1 + a_sts[1], a2, a3);
#pragma unroll
            for (int i = 0; i < 4; i++) {
                uint4 h = *(const uint4*)(qb + i * 8);
                sts128(sb + P_B1 + b_sts[i], h.x, h.y, h.z, h.w);
            }
        }
    }
    __syncthreads();

    for (int c = 0; c < nch; c++) {
        const int p = c & ~1;                       // pair base
        const uint32_t stg = sb + (uint32_t)(((c >> 1) & 1) * P_STAGE);
        const uint32_t stA = stg + ((c & 1) ? P_A1 : P_A0);
        const uint32_t stB = stg + ((c & 1) ? P_B1 : P_B0);
        const uint32_t nstg = sb + (uint32_t)(((~(c >> 1)) & 1) * P_STAGE);
        const bool pf2 = (p + 2) < nch;
        const bool pf3 = (p + 3) < nch;

        if ((c & 1) == 0) {
            // even chunk: handle A(p+2), A(p+3); LDG->STS gap = 2 steps each
            float4 va0, va1, va2, va3;
            if (pf2) {
                const float* qa = pa + (size_t)(p + 2) * KC;
                va0 = *(const float4*)(qa + 0);  va1 = *(const float4*)(qa + 4);
                va2 = *(const float4*)(qa + 8);  va3 = *(const float4*)(qa + 12);
            }
            K16_STEP_HI(0);
            K16_STEP_HI(1);
            if (pf2) {
                cvt_sts8_hi(nstg + P_A0 + a_sts[0], va0, va1);
                cvt_sts8_hi(nstg + P_A0 + a_sts[1], va2, va3);
            }
            if (pf3) {
                const float* qa = pa + (size_t)(p + 3) * KC;
                va0 = *(const float4*)(qa + 0);  va1 = *(const float4*)(qa + 4);
                va2 = *(const float4*)(qa + 8);  va3 = *(const float4*)(qa + 12);
            }
            K16_STEP_HI(2);
            K16_STEP_HI(3);
            if (pf3) {
                cvt_sts8_hi(nstg + P_A1 + a_sts[0], va0, va1);
                cvt_sts8_hi(nstg + P_A1 + a_sts[1], va2, va3);
            }
        } else {
            // odd chunk: handle B(p+2), B(p+3)
            uint4 hb0, hb1, hb2, hb3;
            if (pf2) {
                const __half* qb = pb + (size_t)(p + 2) * KC;
                hb0 = *(const uint4*)(qb + 0);
                hb1 = *(const uint4*)(qb + 8);
                hb2 = *(const uint4*)(qb + 16);
                hb3 = *(const uint4*)(qb + 24);
            }
            K16_STEP_HI(0);
            if (pf2) {
                sts128(nstg + P_B0 + b_sts[0], hb0.x, hb0.y, hb0.z, hb0.w);
                sts128(nstg + P_B0 + b_sts[1], hb1.x, hb1.y, hb1.z, hb1.w);
                sts128(nstg + P_B0 + b_sts[2], hb2.x, hb2.y, hb2.z, hb2.w);
                sts128(nstg + P_B0 + b_sts[3], hb3.x, hb3.y, hb3.z, hb3.w);
            }
            if (pf3) {
                const __half* qb = pb + (size_t)(p + 3) * KC;
                hb0 = *(const uint4*)(qb + 0);
                hb1 = *(const uint4*)(qb + 8);
                hb2 = *(const uint4*)(qb + 16);
                hb3 = *(const uint4*)(qb + 24);
            }
            K16_STEP_HI(1);
            K16_STEP_HI(2);
            if (pf3) {
                sts128(nstg + P_B1 + b_sts[0], hb0.x, hb0.y, hb0.z, hb0.w);
                sts128(nstg + P_B1 + b_sts[1], hb1.x, hb1.y, hb1.z, hb1.w);
                sts128(nstg + P_B1 + b_sts[2], hb2.x, hb2.y, hb2.z, hb2.w);
                sts128(nstg + P_B1 + b_sts[3], hb3.x, hb3.y, hb3.z, hb3.w);
            }
            K16_STEP_HI(3);
            if (c + 1 < nch) __syncthreads();   // stage boundary
        }
    }

    const int g = lane >> 2, t = lane & 3;
#pragma unroll
    for (int mi = 0; mi < 2; mi++) {
        const int grow = m0 + wm * 32 + mi * 16 + g;
#pragma unroll
        for (int nj = 0; nj < 8; nj++) {
            const int gcol = wn * 64 + (nj >> 1) * 16 + (nj & 1) * 8 + 2 * t;
            float2 v0 = make_float2(macc[mi][nj][0] * 0.015625f, macc[mi][nj][1] * 0.015625f);
            float2 v1 = make_float2(macc[mi][nj][2] * 0.015625f, macc[mi][nj][3] * 0.015625f);
            *(float2*)&dst[(size_t)grow * NEXP + gcol]       = v0;
            *(float2*)&dst[(size_t)(grow + 8) * NEXP + gcol] = v1;
        }
    }
}

__global__ __launch_bounds__(THREADS) void gemm_hi(const float* __restrict__ A) {
    extern __shared__ char smem[];
    const uint32_t sb = smem_u32(smem);
    const int tid  = threadIdx.x;
    const int lane = tid & 31;
    const int wid  = tid >> 5;
    const int bid  = blockIdx.x;

    int c  = (int)(((long long)bid * NCOLS_HI) / NSM);
    const int ce = (int)(((long long)(bid + 1) * NCOLS_HI) / NSM);
    const int prev = (bid == 0) ? 0 : (int)(((long long)(bid - 1) * NCOLS_HI) / NSM);

    bool first = true;
    while (c < ce) {
        const int t  = c >> 6;
        const int ts = t << 6;
        const int se = min(ce, ts + 64);
        float* dst;
        if (c == ts)                 dst = g_part0;
        else if (first && prev > ts) dst = g_part2;
        else                         dst = g_part1;
        run_segment_hi(A, dst, t * BM, c - ts, se - c, sb, tid, lane, wid);
        c = se;
        first = false;
    }
}

// ---------------------------------------------------------------------------
// refine: exact fp16x3 for flagged tokens, split-K x4 (unchanged)
// ---------------------------------------------------------------------------
__global__ __launch_bounds__(THREADS, 1) void gemm_refine(const float* __restrict__ A,
                                                          const float* __restrict__ W) {
    const int cnt = g_cnt;
    const int base = blockIdx.y * BM;
    if (base >= cnt) return;

    extern __shared__ char smem[];
    __shared__ int toks[BM];
    const uint32_t sb = smem_u32(smem);
    const int tid  = threadIdx.x;
    const int lane = tid & 31;
    const int wid  = tid >> 5;
    const int wm   = wid & 3;
    const int wn   = wid >> 2;
    const int n0   = blockIdx.x * BN;
    const int kq   = blockIdx.z;
    const int kc0  = kq * NCH_Q * KC;

    if (tid < BM) toks[tid] = g_list[min(base + tid, cnt - 1)];
    __syncthreads();

    const int prow = tid >> 2;
    const int pseg = tid & 3;
    const float* pa = A + (size_t)toks[prow] * HDIM + kc0 + pseg * 16;
    const float* pb = W + (size_t)(n0 + prow) * HDIM + kc0 + pseg * 16;

    uint32_t sts_off[2];
#pragma unroll
    for (int i = 0; i < 2; i++) {
        int g = pseg * 2 + i;
        sts_off[i] = (uint32_t)(prow * 128 + (((g ^ (prow & 7)) & 7) << 4));
    }

    const int r  = lane & 7;
    const int j  = lane >> 3;
    const int jr = j & 1;
    const int jk = j >> 1;
    const int arow = wm * 32 + r + jr * 8;
    const int brow = wn * 32 + r + jk * 8;
    const uint32_t axr = (uint32_t)(arow & 7);
    const uint32_t bxr = (uint32_t)(brow & 7);
    const uint32_t abase = (uint32_t)(arow * 128);
    const uint32_t bbase = (uint32_t)(brow * 128);

    float macc[2][4][4];
    float bacc[2][4][4];
#pragma unroll
    for (int mi = 0; mi < 2; mi++)
#pragma unroll
        for (int nj = 0; nj < 4; nj++)
#pragma unroll
            for (int q = 0; q < 4; q++) { macc[mi][nj][q] = 0.0f; bacc[mi][nj][q] = 0.0f; }

    {
        float4 a0 = *(const float4*)(pa + 0), a1 = *(const float4*)(pa + 4);
        float4 a2 = *(const float4*)(pa + 8), a3 = *(const float4*)(pa + 12);
        float4 b0 = *(const float4*)(pb + 0), b1 = *(const float4*)(pb + 4);
        float4 b2 = *(const float4*)(pb + 8), b3 = *(const float4*)(pb + 12);
        b0.x *= 64.f; b0.y *= 64.f; b0.z *= 64.f; b0.w *= 64.f;
        b1.x *= 64.f; b1.y *= 64.f; b1.z *= 64.f; b1.w *= 64.f;
        b2.x *= 64.f; b2.y *= 64.f; b2.z *= 64.f; b2.w *= 64.f;
        b3.x *= 64.f; b3.y *= 64.f; b3.z *= 64.f; b3.w *= 64.f;
        cvt_sts8(sb + AH_OFF + sts_off[0], sb + AL_OFF + sts_off[0], a0, a1);
        cvt_sts8(sb + AH_OFF + sts_off[1], sb + AL_OFF + sts_off[1], a2, a3);
        cvt_sts8(sb + BH_OFF + sts_off[0], sb + BL_OFF + sts_off[0], b0, b1);
        cvt_sts8(sb + BH_OFF + sts_off[1], sb + BL_OFF + sts_off[1], b2, b3);
    }
    __syncthreads();

    for (int c = 0; c < NCH_Q; c++) {
        const uint32_t st = sb + (uint32_t)((c & 1) * STAGE_BYTES);
        const bool more = (c + 1 < NCH_Q);

        float4 va[4];
        if (more) {
            const float* qa = pa + (size_t)(c + 1) * KC;
#pragma unroll
            for (int i = 0; i < 4; i++) va[i] = *(const float4*)(qa + i * 4);
        }

#pragma unroll
        for (int k16 = 0; k16 < 2; k16++) K16_STEP(k16);

        float4 vb[4];
        if (more) {
            const float* qb = pb + (size_t)(c + 1) * KC;
#pragma unroll
            for (int i = 0; i < 4; i++) vb[i] = *(const float4*)(qb + i * 4);
        }

#pragma unroll
        for (int k16 = 2; k16 < 4; k16++) K16_STEP(k16);

        if (c & 1) {
#pragma unroll
            for (int mi = 0; mi < 2; mi++)
#pragma unroll
                for (int nj = 0; nj < 4; nj++)
#pragma unroll
                    for (int q = 0; q < 4; q++) {
                        macc[mi][nj][q] += bacc[mi][nj][q];
                        bacc[mi][nj][q] = 0.0f;
                    }
        }

        if (more) {
            const uint32_t nst = sb + (uint32_t)(((c + 1) & 1) * STAGE_BYTES);
#pragma unroll
            for (int i = 0; i < 4; i++) {
                vb[i].x *= 64.f; vb[i].y *= 64.f; vb[i].z *= 64.f; vb[i].w *= 64.f;
            }
            cvt_sts8(nst + AH_OFF + sts_off[0], nst + AL_OFF + sts_off[0], va[0], va[1]);
            cvt_sts8(nst + AH_OFF + sts_off[1], nst + AL_OFF + sts_off[1], va[2], va[3]);
            cvt_sts8(nst + BH_OFF + sts_off[0], nst + BL_OFF + sts_off[0], vb[0], vb[1]);
            cvt_sts8(nst + BH_OFF + sts_off[1], nst + BL_OFF + sts_off[1], vb[2], vb[3]);
            __syncthreads();
        }
    }

    float* dst = g_rbuf[kq];
    const int g = lane >> 2, t = lane & 3;
#pragma unroll
    for (int mi = 0; mi < 2; mi++) {
        const int r0 = wm * 32 + mi * 16 + g;
        const int tok0 = toks[r0];
        const int tok8 = toks[r0 + 8];
#pragma unroll
        for (int nj = 0; nj < 4; nj++) {
            const int gcol = n0 + wn * 32 + (nj >> 1) * 16 + (nj & 1) * 8 + 2 * t;
            float2 v0 = make_float2(macc[mi][nj][0] * 0.015625f, macc[mi][nj][1] * 0.015625f);
            float2 v1 = make_float2(macc[mi][nj][2] * 0.015625f, macc[mi][nj][3] * 0.015625f);
            *(float2*)&dst[(size_t)tok0 * NEXP + gcol] = v0;
            *(float2*)&dst[(size_t)tok8 * NEXP + gcol] = v1;
        }
    }
}

// ---------------------------------------------------------------------------
// routing core (verified semantics)
// ---------------------------------------------------------------------------
__device__ __forceinline__ void route_core(int token, const float* xs,
                                           const float* __restrict__ bias,
                                           void* __restrict__ out, int mode,
                                           int lane, bool check_margin) {
    const float* bp = bias + lane * 8;
    float4 b0 = *(const float4*)bp;
    float4 b1 = *(const float4*)(bp + 4);
    float bs[8] = {b0.x, b0.y, b0.z, b0.w, b1.x, b1.y, b1.z, b1.w};

    float s[8], sc[8];
#pragma unroll
    for (int jj = 0; jj < 8; jj++) {
        s[jj]  = 1.0f / (1.0f + expf(-xs[jj]));
        sc[jj] = s[jj] + bs[jj];
    }

    float m1 = -1e30f, m2 = -1e30f;
#pragma unroll
    for (int jj = 0; jj < 8; jj++) {
        float x = sc[jj];
        if (x > m1) { m2 = m1; m1 = x; }
        else if (x > m2) { m2 = x; }
    }
#pragma unroll
    for (int d = 1; d <= 2; d <<= 1) {
        float o1 = __shfl_xor_sync(0xffffffffu, m1, d);
        float o2 = __shfl_xor_sync(0xffffffffu, m2, d);
        float n2 = fmaxf(fminf(m1, o1), fmaxf(m2, o2));
        m1 = fmaxf(m1, o1);
        m2 = n2;
    }
    float gs = m1 + m2;

    float gsv[8];
#pragma unroll
    for (int gg = 0; gg < 8; gg++) gsv[gg] = __shfl_sync(0xffffffffu, gs, gg * 4);

    unsigned gsel = 0;
    float pick4 = 0.0f;
#pragma unroll
    for (int rr = 0; rr < TOPK_GRP; rr++) {
        float best = -1e30f; int bi = 0;
#pragma unroll
        for (int gg = 0; gg < 8; gg++) {
            float v = ((gsel >> gg) & 1u) ? -1e30f : gsv[gg];
            if (v > best) { best = v; bi = gg; }
        }
        gsel |= 1u << bi;
        if (rr == TOPK_GRP - 1) pick4 = best;
    }
    float best5 = -1e30f;
#pragma unroll
    for (int gg = 0; gg < 8; gg++) {
        float v = ((gsel >> gg) & 1u) ? -1e30f : gsv[gg];
        best5 = fmaxf(best5, v);
    }
    const float margin_g = pick4 - best5;

    const bool insel = (gsel >> (lane >> 2)) & 1u;
    float mv[8];
#pragma unroll
    for (int jj = 0; jj < 8; jj++) mv[jj] = insel ? sc[jj] : 0.0f;

    int   oi[8];
    float ow[8];
    float prevbv = 0.0f, mingap = 1e30f;
#pragma unroll
    for (int rr = 0; rr < TOPK; rr++) {
        float lb = mv[0]; int lj = 0;
#pragma unroll
        for (int jj = 1; jj < 8; jj++)
            if (mv[jj] > lb) { lb = mv[jj]; lj = jj; }
        float bv = lb;
        int   be = lane * 8 + lj;
#pragma unroll
        for (int off = 16; off >= 1; off >>= 1) {
            float ov = __shfl_xor_sync(0xffffffffu, bv, off);
            int   oe = __shfl_xor_sync(0xffffffffu, be, off);
            if (ov > bv || (ov == bv && oe < be)) { bv = ov; be = oe; }
        }
        oi[rr] = be;
        if (rr > 0) mingap = fminf(mingap, prevbv - bv);
        prevbv = bv;
        const int jj2 = be & 7;
        float sj = s[0];
#pragma unroll
        for (int jj = 1; jj < 8; jj++)
            if (jj2 == jj) sj = s[jj];
        ow[rr] = __shfl_sync(0xffffffffu, sj, be >> 3);
        if (lane == (be >> 3)) {
#pragma unroll
            for (int jj = 0; jj < 8; jj++)
                if (jj2 == jj) mv[jj] = -1e30f;
        }
    }

    bool flag = false;
    if (check_margin) {
        float lb = mv[0];
#pragma unroll
        for (int jj = 1; jj < 8; jj++) lb = fmaxf(lb, mv[jj]);
        float bv9 = lb;
#pragma unroll
        for (int off = 16; off >= 1; off >>= 1)
            bv9 = fmaxf(bv9, __shfl_xor_sync(0xffffffffu, bv9, off));
        mingap = fminf(mingap, prevbv - bv9);
        flag = (margin_g < TH_GRP) || (mingap < TH_EXP);
    }

    if (lane == 0) {
        if (flag) {
            int pos = atomicAdd(&g_cnt, 1);
            g_list[pos] = token;
        } else {
            float sum = 0.0f;
#pragma unroll
            for (int rr = 0; rr < TOPK; rr++) sum += ow[rr];
            const float den = sum + 1e-20f;
            if (mode == 0) {
                float* of = (float*)out;
#pragma unroll
                for (int rr = 0; rr < TOPK; rr++) {
                    of[(size_t)token * TOPK + rr] = (float)oi[rr];
                    of[(size_t)T_TOK * TOPK + (size_t)token * TOPK + rr] =
                        (ow[rr] / den) * 2.5f;
                }
            } else {
                int* op = (int*)out;
#pragma unroll
                for (int rr = 0; rr < TOPK; rr++) op[(size_t)token * TOPK + rr] = oi[rr];
            }
        }
    }
}

__global__ __launch_bounds__(256) void route_flag(const float* __restrict__ bias,
                                                  void* __restrict__ out, int mode) {
    const int warp = (blockIdx.x * blockDim.x + threadIdx.x) >> 5;
    const int lane = threadIdx.x & 31;
    if (warp >= T_TOK) return;

    const float* lg0 = g_part0 + (size_t)warp * NEXP + lane * 8;
    const float* lg1 = g_part1 + (size_t)warp * NEXP + lane * 8;
    const float* lg2 = g_part2 + (size_t)warp * NEXP + lane * 8;
    float4 x0 = *(const float4*)lg0;
    float4 x1 = *(const float4*)(lg0 + 4);
    float4 y0 = *(const float4*)lg1;
    float4 y1 = *(const float4*)(lg1 + 4);
    float4 z0 = *(const float4*)lg2;
    float4 z1 = *(const float4*)(lg2 + 4);
    float xs[8] = {x0.x + y0.x + z0.x, x0.y + y0.y + z0.y,
                   x0.z + y0.z + z0.z, x0.w + y0.w + z0.w,
                   x1.x + y1.x + z1.x, x1.y + y1.y + z1.y,
                   x1.z + y1.z + z1.z, x1.w + y1.w + z1.w};
    route_core(warp, xs, bias, out, mode, lane, true);
}

__global__ __launch_bounds__(256) void route_final(const float* __restrict__ bias,
                                                   void* __restrict__ out, int mode) {
    const int w = (blockIdx.x * blockDim.x + threadIdx.x) >> 5;
    const int lane = threadIdx.x & 31;
    if (w >= g_cnt) return;
    const int token = g_list[w];

    float xs[8] = {0, 0, 0, 0, 0, 0, 0, 0};
#pragma unroll
    for (int kq = 0; kq < KSPLIT; kq++) {
        const float* lg = g_rbuf[kq] + (size_t)token * NEXP + lane * 8;
        float4 a = *(const float4*)lg;
        float4 b = *(const float4*)(lg + 4);
        xs[0] += a.x; xs[1] += a.y; xs[2] += a.z; xs[3] += a.w;
        xs[4] += b.x; xs[5] += b.y; xs[6] += b.z; xs[7] += b.w;
    }
    route_core(token, xs, bias, out, mode, lane, false);
}

extern "C" void kernel_launch(void* const* d_in, const int* in_sizes, int n_in,
                              void* d_out, int out_size) {
    const float* hs   = (const float*)d_in[0];
    const float* w    = (const float*)d_in[1];
    const float* bias = (const float*)d_in[2];

    cudaFuncSetAttribute(gemm_hi, cudaFuncAttributeMaxDynamicSharedMemorySize, P_SM_TOTAL);
    cudaFuncSetAttribute(gemm_refine, cudaFuncAttributeMaxDynamicSharedMemorySize, SM_TOTAL);

    const int mode = (out_size >= 2 * T_TOK * TOPK) ? 0 : 1;

    w_convert<<<(NEXP * HDIM / 4) / 256, 256>>>(w);
    gemm_hi<<<NSM, THREADS, P_SM_TOTAL>>>(hs);
    route_flag<<<T_TOK / 8, 256>>>(bias, d_out, mode);
    gemm_refine<<<dim3(2, 128, KSPLIT), THREADS, SM_TOTAL>>>(hs, w);
    route_final<<<T_TOK / 8, 256>>>(bias, d_out, mode);
}

// round 16
// speedup vs baseline: 1.0330x; 1.0330x over previous
#include <cuda_runtime.h>
#include <cuda_fp16.h>
#include <math.h>
#include <stdint.h>

#define T_TOK 16384
#define HDIM  4096
#define NEXP  256
#define TOPK  8
#define TOPK_GRP 4

#define BM 128
#define BN 128
#define KC 64
#define NSM 148
#define THREADS 512

// refine (full 3-term) stage layout: AH AL BH BL = 64KB; 3 stages = 192KB
#define R_AH 0
#define R_AL 16384
#define R_BH 32768
#define R_BL 49152
#define R_STAGE 65536
#define R_SM_TOTAL (3 * R_STAGE)

// phase-1 (hi-only, 128x256 tile, 2 chunks per stage)
#define P_A0 0
#define P_A1 16384
#define P_B0 32768
#define P_B1 65536
#define P_STAGE 98304
#define P_SM_TOTAL (2 * P_STAGE)
#define NCOLS_HI (128 * 64)

// margin thresholds (score space) — validated R10-R15
#define TH_EXP 8e-4f
#define TH_GRP 1.6e-3f

#define KSPLIT 4
#define NCH_Q  (HDIM / KC / KSPLIT)

__device__ float g_part0[(size_t)T_TOK * NEXP];
__device__ float g_part1[(size_t)T_TOK * NEXP];
__device__ float g_part2[(size_t)T_TOK * NEXP];
__device__ float g_rbuf[KSPLIT][(size_t)T_TOK * NEXP];
__device__ int   g_cnt;
__device__ int   g_list[T_TOK];
__device__ __align__(16) __half g_wh[(size_t)NEXP * HDIM];  // W*64 hi
__device__ __align__(16) __half g_wl[(size_t)NEXP * HDIM];  // W*64 lo

// ---------------- helpers ----------------
__device__ __forceinline__ uint32_t smem_u32(const void* p) {
    uint32_t a;
    asm("{ .reg .u64 t; cvta.to.shared.u64 t, %1; cvt.u32.u64 %0, t; }" : "=r"(a) : "l"(p));
    return a;
}
__device__ __forceinline__ void sts128(uint32_t addr, uint32_t x, uint32_t y,
                                       uint32_t z, uint32_t w) {
    asm volatile("st.shared.v4.b32 [%0], {%1, %2, %3, %4};"
                 :: "r"(addr), "r"(x), "r"(y), "r"(z), "r"(w) : "memory");
}
__device__ __forceinline__ void ldsm4(uint32_t* r, uint32_t addr) {
    asm volatile("ldmatrix.sync.aligned.m8n8.x4.shared.b16 {%0, %1, %2, %3}, [%4];"
                 : "=r"(r[0]), "=r"(r[1]), "=r"(r[2]), "=r"(r[3]) : "r"(addr));
}
__device__ __forceinline__ void mma_f16(float* c, const uint32_t* a,
                                        uint32_t b0, uint32_t b1) {
    asm volatile(
        "mma.sync.aligned.m16n8k16.row.col.f32.f16.f16.f32 "
        "{%0, %1, %2, %3}, {%4, %5, %6, %7}, {%8, %9}, {%0, %1, %2, %3};"
        : "+f"(c[0]), "+f"(c[1]), "+f"(c[2]), "+f"(c[3])
        : "r"(a[0]), "r"(a[1]), "r"(a[2]), "r"(a[3]), "r"(b0), "r"(b1));
}
__device__ __forceinline__ void split2(float a, float b, uint32_t& h, uint32_t& l) {
    __half ha = __float2half_rn(a), hb = __float2half_rn(b);
    float ra = a - __half2float(ha);
    float rb = b - __half2float(hb);
    __half2 ph = __halves2half2(ha, hb);
    __half2 pl = __halves2half2(__float2half_rn(ra), __float2half_rn(rb));
    h = *reinterpret_cast<uint32_t*>(&ph);
    l = *reinterpret_cast<uint32_t*>(&pl);
}
__device__ __forceinline__ uint32_t packh2(float a, float b) {
    __half2 p = __floats2half2_rn(a, b);
    return *reinterpret_cast<uint32_t*>(&p);
}
__device__ __forceinline__ void cvt_sts8(uint32_t addr_hi, uint32_t addr_lo,
                                         float4 v0, float4 v1) {
    uint32_t h[4], l[4];
    split2(v0.x, v0.y, h[0], l[0]);
    split2(v0.z, v0.w, h[1], l[1]);
    split2(v1.x, v1.y, h[2], l[2]);
    split2(v1.z, v1.w, h[3], l[3]);
    sts128(addr_hi, h[0], h[1], h[2], h[3]);
    sts128(addr_lo, l[0], l[1], l[2], l[3]);
}
__device__ __forceinline__ void cvt_sts8_hi(uint32_t addr, float4 v0, float4 v1) {
    sts128(addr, packh2(v0.x, v0.y), packh2(v0.z, v0.w),
           packh2(v1.x, v1.y), packh2(v1.z, v1.w));
}

// W preconvert: hi AND lo fp16 of W*64; also resets g_cnt
__global__ __launch_bounds__(256) void w_convert(const float* __restrict__ W) {
    if (blockIdx.x == 0 && threadIdx.x == 0) g_cnt = 0;
    const int idx = blockIdx.x * 256 + threadIdx.x;
    float4 v = ((const float4*)W)[idx];
    v.x *= 64.f; v.y *= 64.f; v.z *= 64.f; v.w *= 64.f;
    uint32_t h0, l0, h1, l1;
    split2(v.x, v.y, h0, l0);
    split2(v.z, v.w, h1, l1);
    ((uint2*)g_wh)[idx] = make_uint2(h0, h1);
    ((uint2*)g_wl)[idx] = make_uint2(l0, l1);
}

// full 3-term k16 step on refine stage `st`
#define K16_STEP_R(K16)                                                        \
    do {                                                                       \
        uint32_t ah[2][4], al[2][4], bh[2][4], bl[2][4];                       \
        const uint32_t asg = (uint32_t)((((K16) * 2 + jk) ^ axr) << 4);        \
        const uint32_t bsg = (uint32_t)((((K16) * 2 + jr) ^ bxr) << 4);        \
        _Pragma("unroll")                                                      \
        for (int mi = 0; mi < 2; mi++) {                                       \
            const uint32_t ra = abase + (uint32_t)(mi * 2048) + asg;           \
            ldsm4(ah[mi], st + R_AH + ra);                                     \
            ldsm4(al[mi], st + R_AL + ra);                                     \
        }                                                                      \
        _Pragma("unroll")                                                      \
        for (int q = 0; q < 2; q++) {                                          \
            const uint32_t rb = bbase + (uint32_t)(q * 2048) + bsg;            \
            ldsm4(bh[q], st + R_BH + rb);                                      \
            ldsm4(bl[q], st + R_BL + rb);                                      \
        }                                                                      \
        _Pragma("unroll")                                                      \
        for (int mi = 0; mi < 2; mi++)                                         \
            _Pragma("unroll")                                                  \
            for (int nj = 0; nj < 4; nj++) {                                   \
                const int q = nj >> 1, s2 = (nj & 1) * 2;                      \
                mma_f16(bacc[mi][nj], ah[mi], bh[q][s2], bh[q][s2 + 1]);       \
            }                                                                  \
        _Pragma("unroll")                                                      \
        for (int mi = 0; mi < 2; mi++)                                         \
            _Pragma("unroll")                                                  \
            for (int nj = 0; nj < 4; nj++) {                                   \
                const int q = nj >> 1, s2 = (nj & 1) * 2;                      \
                mma_f16(bacc[mi][nj], ah[mi], bl[q][s2], bl[q][s2 + 1]);       \
            }                                                                  \
        _Pragma("unroll")                                                      \
        for (int mi = 0; mi < 2; mi++)                                         \
            _Pragma("unroll")                                                  \
            for (int nj = 0; nj < 4; nj++) {                                   \
                const int q = nj >> 1, s2 = (nj & 1) * 2;                      \
                mma_f16(bacc[mi][nj], al[mi], bh[q][s2], bh[q][s2 + 1]);       \
            }                                                                  \
    } while (0)

// hi-only k16 step, warp tile 32x64 (unchanged from R14/R15)
#define K16_STEP_HI(K16)                                                       \
    do {                                                                       \
        uint32_t ah[2][4], bh[4][4];                                           \
        const uint32_t asg = (uint32_t)((((K16) * 2 + jk) ^ axr) << 4);        \
        const uint32_t bsg = (uint32_t)((((K16) * 2 + jr) ^ bxr) << 4);        \
        _Pragma("unroll")                                                      \
        for (int mi = 0; mi < 2; mi++)                                         \
            ldsm4(ah[mi], stA + abase + (uint32_t)(mi * 2048) + asg);          \
        _Pragma("unroll")                                                      \
        for (int p = 0; p < 4; p++)                                            \
            ldsm4(bh[p], stB + bbase + (uint32_t)(p * 2048) + bsg);            \
        _Pragma("unroll")                                                      \
        for (int mi = 0; mi < 2; mi++)                                         \
            _Pragma("unroll")                                                  \
            for (int nj = 0; nj < 8; nj++) {                                   \
                const int p = nj >> 1, s2 = (nj & 1) * 2;                      \
                mma_f16(macc[mi][nj], ah[mi], bh[p][s2], bh[p][s2 + 1]);       \
            }                                                                  \
    } while (0)

// ---------------------------------------------------------------------------
// phase-1 segment (unchanged from R15)
// ---------------------------------------------------------------------------
__device__ __forceinline__ void run_segment_hi(
    const float* __restrict__ A,
    float* __restrict__ dst, int m0, int lc0, int nch,
    uint32_t sb, int tid, int lane, int wid)
{
    __syncthreads();

    const int wm = wid & 3;
    const int wn = wid >> 2;

    const int parow = tid >> 2;
    const int paseg = tid & 3;
    const float* pa = A + (size_t)(m0 + parow) * HDIM + lc0 * KC + paseg * 16;
    uint32_t a_sts[2];
#pragma unroll
    for (int i = 0; i < 2; i++) {
        int g = paseg * 2 + i;
        a_sts[i] = (uint32_t)(parow * 128 + (((g ^ (parow & 7)) & 7) << 4));
    }
    const int pbrow = tid >> 1;
    const int pbseg = tid & 1;
    const __half* pb = g_wh + (size_t)pbrow * HDIM + lc0 * KC + pbseg * 32;
    uint32_t b_sts[4];
#pragma unroll
    for (int i = 0; i < 4; i++) {
        int g = pbseg * 4 + i;
        b_sts[i] = (uint32_t)(pbrow * 128 + (((g ^ (pbrow & 7)) & 7) << 4));
    }

    const int r  = lane & 7;
    const int j  = lane >> 3;
    const int jr = j & 1;
    const int jk = j >> 1;
    const int arow = wm * 32 + r + jr * 8;
    const int brow = wn * 64 + r + jk * 8;
    const uint32_t axr = (uint32_t)(arow & 7);
    const uint32_t bxr = (uint32_t)(brow & 7);
    const uint32_t abase = (uint32_t)(arow * 128);
    const uint32_t bbase = (uint32_t)(brow * 128);

    float macc[2][8][4];
#pragma unroll
    for (int mi = 0; mi < 2; mi++)
#pragma unroll
        for (int nj = 0; nj < 8; nj++)
#pragma unroll
            for (int q = 0; q < 4; q++) macc[mi][nj][q] = 0.0f;

    {
        float4 a0 = *(const float4*)(pa + 0), a1 = *(const float4*)(pa + 4);
        float4 a2 = *(const float4*)(pa + 8), a3 = *(const float4*)(pa + 12);
        cvt_sts8_hi(sb + P_A0 + a_sts[0], a0, a1);
        cvt_sts8_hi(sb + P_A0 + a_sts[1], a2, a3);
#pragma unroll
        for (int i = 0; i < 4; i++) {
            uint4 h = *(const uint4*)(pb + i * 8);
            sts128(sb + P_B0 + b_sts[i], h.x, h.y, h.z, h.w);
        }
        if (nch > 1) {
            const float* qa = pa + KC;
            const __half* qb = pb + KC;
            a0 = *(const float4*)(qa + 0); a1 = *(const float4*)(qa + 4);
            a2 = *(const float4*)(qa + 8); a3 = *(const float4*)(qa + 12);
            cvt_sts8_hi(sb + P_A1 + a_sts[0], a0, a1);
            cvt_sts8_hi(sb + P_A1 + a_sts[1], a2, a3);
#pragma unroll
            for (int i = 0; i < 4; i++) {
                uint4 h = *(const uint4*)(qb + i * 8);
                sts128(sb + P_B1 + b_sts[i], h.x, h.y, h.z, h.w);
            }
        }
    }
    __syncthreads();

    for (int c = 0; c < nch; c++) {
        const int p = c & ~1;
        const uint32_t stg = sb + (uint32_t)(((c >> 1) & 1) * P_STAGE);
        const uint32_t stA = stg + ((c & 1) ? P_A1 : P_A0);
        const uint32_t stB = stg + ((c & 1) ? P_B1 : P_B0);
        const uint32_t nstg = sb + (uint32_t)(((~(c >> 1)) & 1) * P_STAGE);
        const bool pf2 = (p + 2) < nch;
        const bool pf3 = (p + 3) < nch;

        if ((c & 1) == 0) {
            float4 va0, va1, va2, va3;
            if (pf2) {
                const float* qa = pa + (size_t)(p + 2) * KC;
                va0 = *(const float4*)(qa + 0);  va1 = *(const float4*)(qa + 4);
                va2 = *(const float4*)(qa + 8);  va3 = *(const float4*)(qa + 12);
            }
            K16_STEP_HI(0);
            K16_STEP_HI(1);
            if (pf2) {
                cvt_sts8_hi(nstg + P_A0 + a_sts[0], va0, va1);
                cvt_sts8_hi(nstg + P_A0 + a_sts[1], va2, va3);
            }
            if (pf3) {
                const float* qa = pa + (size_t)(p + 3) * KC;
                va0 = *(const float4*)(qa + 0);  va1 = *(const float4*)(qa + 4);
                va2 = *(const float4*)(qa + 8);  va3 = *(const float4*)(qa + 12);
            }
            K16_STEP_HI(2);
            K16_STEP_HI(3);
            if (pf3) {
                cvt_sts8_hi(nstg + P_A1 + a_sts[0], va0, va1);
                cvt_sts8_hi(nstg + P_A1 + a_sts[1], va2, va3);
            }
        } else {
            uint4 hb0, hb1, hb2, hb3;
            if (pf2) {
                const __half* qb = pb + (size_t)(p + 2) * KC;
                hb0 = *(const uint4*)(qb + 0);
                hb1 = *(const uint4*)(qb + 8);
                hb2 = *(const uint4*)(qb + 16);
                hb3 = *(const uint4*)(qb + 24);
            }
            K16_STEP_HI(0);
            if (pf2) {
                sts128(nstg + P_B0 + b_sts[0], hb0.x, hb0.y, hb0.z, hb0.w);
                sts128(nstg + P_B0 + b_sts[1], hb1.x, hb1.y, hb1.z, hb1.w);
                sts128(nstg + P_B0 + b_sts[2], hb2.x, hb2.y, hb2.z, hb2.w);
                sts128(nstg + P_B0 + b_sts[3], hb3.x, hb3.y, hb3.z, hb3.w);
            }
            if (pf3) {
                const __half* qb = pb + (size_t)(p + 3) * KC;
                hb0 = *(const uint4*)(qb + 0);
                hb1 = *(const uint4*)(qb + 8);
                hb2 = *(const uint4*)(qb + 16);
                hb3 = *(const uint4*)(qb + 24);
            }
            K16_STEP_HI(1);
            K16_STEP_HI(2);
            if (pf3) {
                sts128(nstg + P_B1 + b_sts[0], hb0.x, hb0.y, hb0.z, hb0.w);
                sts128(nstg + P_B1 + b_sts[1], hb1.x, hb1.y, hb1.z, hb1.w);
                sts128(nstg + P_B1 + b_sts[2], hb2.x, hb2.y, hb2.z, hb2.w);
                sts128(nstg + P_B1 + b_sts[3], hb3.x, hb3.y, hb3.z, hb3.w);
            }
            K16_STEP_HI(3);
            if (c + 1 < nch) __syncthreads();
        }
    }

    const int g = lane >> 2, t = lane & 3;
#pragma unroll
    for (int mi = 0; mi < 2; mi++) {
        const int grow = m0 + wm * 32 + mi * 16 + g;
#pragma unroll
        for (int nj = 0; nj < 8; nj++) {
            const int gcol = wn * 64 + (nj >> 1) * 16 + (nj & 1) * 8 + 2 * t;
            float2 v0 = make_float2(macc[mi][nj][0] * 0.015625f, macc[mi][nj][1] * 0.015625f);
            float2 v1 = make_float2(macc[mi][nj][2] * 0.015625f, macc[mi][nj][3] * 0.015625f);
            *(float2*)&dst[(size_t)grow * NEXP + gcol]       = v0;
            *(float2*)&dst[(size_t)(grow + 8) * NEXP + gcol] = v1;
        }
    }
}

__global__ __launch_bounds__(THREADS) void gemm_hi(const float* __restrict__ A) {
    extern __shared__ char smem[];
    const uint32_t sb = smem_u32(smem);
    const int tid  = threadIdx.x;
    const int lane = tid & 31;
    const int wid  = tid >> 5;
    const int bid  = blockIdx.x;

    int c  = (int)(((long long)bid * NCOLS_HI) / NSM);
    const int ce = (int)(((long long)(bid + 1) * NCOLS_HI) / NSM);
    const int prev = (bid == 0) ? 0 : (int)(((long long)(bid - 1) * NCOLS_HI) / NSM);

    bool first = true;
    while (c < ce) {
        const int t  = c >> 6;
        const int ts = t << 6;
        const int se = min(ce, ts + 64);
        float* dst;
        if (c == ts)                 dst = g_part0;
        else if (first && prev > ts) dst = g_part2;
        else                         dst = g_part1;
        run_segment_hi(A, dst, t * BM, c - ts, se - c, sb, tid, lane, wid);
        c = se;
        first = false;
    }
}

// ---------------------------------------------------------------------------
// refine: exact fp16x3 for flagged tokens, split-K x4, 3-stage pipeline,
// B from preconverted g_wh/g_wl. grid (2, 128, KSPLIT), 512 threads.
// ---------------------------------------------------------------------------
__global__ __launch_bounds__(THREADS, 1) void gemm_refine(const float* __restrict__ A) {
    const int cnt = g_cnt;
    const int base = blockIdx.y * BM;
    if (base >= cnt) return;

    extern __shared__ char smem[];
    __shared__ int toks[BM];
    const uint32_t sb = smem_u32(smem);
    const int tid  = threadIdx.x;
    const int lane = tid & 31;
    const int wid  = tid >> 5;
    const int wm   = wid & 3;
    const int wn   = wid >> 2;
    const int n0   = blockIdx.x * BN;
    const int kq   = blockIdx.z;
    const int kc0  = kq * NCH_Q * KC;

    if (tid < BM) toks[tid] = g_list[min(base + tid, cnt - 1)];
    __syncthreads();

    const int prow = tid >> 2;
    const int pseg = tid & 3;
    const float* pa  = A    + (size_t)toks[prow] * HDIM + kc0 + pseg * 16;
    const __half* pbh = g_wh + (size_t)(n0 + prow) * HDIM + kc0 + pseg * 16;
    const __half* pbl = g_wl + (size_t)(n0 + prow) * HDIM + kc0 + pseg * 16;

    uint32_t sts_off[2];
#pragma unroll
    for (int i = 0; i < 2; i++) {
        int g = pseg * 2 + i;
        sts_off[i] = (uint32_t)(prow * 128 + (((g ^ (prow & 7)) & 7) << 4));
    }

    const int r  = lane & 7;
    const int j  = lane >> 3;
    const int jr = j & 1;
    const int jk = j >> 1;
    const int arow = wm * 32 + r + jr * 8;
    const int brow = wn * 32 + r + jk * 8;
    const uint32_t axr = (uint32_t)(arow & 7);
    const uint32_t bxr = (uint32_t)(brow & 7);
    const uint32_t abase = (uint32_t)(arow * 128);
    const uint32_t bbase = (uint32_t)(brow * 128);

    float macc[2][4][4];
    float bacc[2][4][4];
#pragma unroll
    for (int mi = 0; mi < 2; mi++)
#pragma unroll
        for (int nj = 0; nj < 4; nj++)
#pragma unroll
            for (int q = 0; q < 4; q++) { macc[mi][nj][q] = 0.0f; bacc[mi][nj][q] = 0.0f; }

    // prologue: fill stages 0,1 with chunks 0,1
#pragma unroll
    for (int pc = 0; pc < 2; pc++) {
        const uint32_t stg = sb + (uint32_t)(pc * R_STAGE);
        const float* qa = pa + (size_t)pc * KC;
        float4 a0 = *(const float4*)(qa + 0), a1 = *(const float4*)(qa + 4);
        float4 a2 = *(const float4*)(qa + 8), a3 = *(const float4*)(qa + 12);
        cvt_sts8(stg + R_AH + sts_off[0], stg + R_AL + sts_off[0], a0, a1);
        cvt_sts8(stg + R_AH + sts_off[1], stg + R_AL + sts_off[1], a2, a3);
        const __half* qh = pbh + (size_t)pc * KC;
        const __half* ql = pbl + (size_t)pc * KC;
        uint4 h0 = *(const uint4*)qh, h1 = *(const uint4*)(qh + 8);
        uint4 l0 = *(const uint4*)ql, l1 = *(const uint4*)(ql + 8);
        sts128(stg + R_BH + sts_off[0], h0.x, h0.y, h0.z, h0.w);
        sts128(stg + R_BH + sts_off[1], h1.x, h1.y, h1.z, h1.w);
        sts128(stg + R_BL + sts_off[0], l0.x, l0.y, l0.z, l0.w);
        sts128(stg + R_BL + sts_off[1], l1.x, l1.y, l1.z, l1.w);
    }
    __syncthreads();

    for (int c = 0; c < NCH_Q; c++) {
        const uint32_t st  = sb + (uint32_t)((c % 3) * R_STAGE);
        const uint32_t nst = sb + (uint32_t)(((c + 2) % 3) * R_STAGE);
        const bool pf = (c + 2) < NCH_Q;

        // A prefetch for c+2 (issued at chunk top; STS 2 steps later)
        float4 va0, va1, va2, va3;
        if (pf) {
            const float* qa = pa + (size_t)(c + 2) * KC;
            va0 = *(const float4*)(qa + 0);  va1 = *(const float4*)(qa + 4);
            va2 = *(const float4*)(qa + 8);  va3 = *(const float4*)(qa + 12);
        }

        K16_STEP_R(0);
        K16_STEP_R(1);

        if (pf) {
            cvt_sts8(nst + R_AH + sts_off[0], nst + R_AL + sts_off[0], va0, va1);
            cvt_sts8(nst + R_AH + sts_off[1], nst + R_AL + sts_off[1], va2, va3);
        }

        // B prefetch for c+2 (preconverted fp16, L2-resident)
        uint4 hb0, hb1, lb0, lb1;
        if (pf) {
            const __half* qh = pbh + (size_t)(c + 2) * KC;
            const __half* ql = pbl + (size_t)(c + 2) * KC;
            hb0 = *(const uint4*)qh;      hb1 = *(const uint4*)(qh + 8);
            lb0 = *(const uint4*)ql;      lb1 = *(const uint4*)(ql + 8);
        }

        K16_STEP_R(2);

        if (pf) {
            sts128(nst + R_BH + sts_off[0], hb0.x, hb0.y, hb0.z, hb0.w);
            sts128(nst + R_BH + sts_off[1], hb1.x, hb1.y, hb1.z, hb1.w);
            sts128(nst + R_BL + sts_off[0], lb0.x, lb0.y, lb0.z, lb0.w);
            sts128(nst + R_BL + sts_off[1], lb1.x, lb1.y, lb1.z, lb1.w);
        }

        K16_STEP_R(3);

        if (c & 1) {
#pragma unroll
            for (int mi = 0; mi < 2; mi++)
#pragma unroll
                for (int nj = 0; nj < 4; nj++)
#pragma unroll
                    for (int q = 0; q < 4; q++) {
                        macc[mi][nj][q] += bacc[mi][nj][q];
                        bacc[mi][nj][q] = 0.0f;
                    }
        }

        if (c + 1 < NCH_Q) __syncthreads();
    }

    float* dst = g_rbuf[kq];
    const int g = lane >> 2, t = lane & 3;
#pragma unroll
    for (int mi = 0; mi < 2; mi++) {
        const int r0 = wm * 32 + mi * 16 + g;
        const int tok0 = toks[r0];
        const int tok8 = toks[r0 + 8];
#pragma unroll
        for (int nj = 0; nj < 4; nj++) {
            const int gcol = n0 + wn * 32 + (nj >> 1) * 16 + (nj & 1) * 8 + 2 * t;
            float2 v0 = make_float2(macc[mi][nj][0] * 0.015625f, macc[mi][nj][1] * 0.015625f);
            float2 v1 = make_float2(macc[mi][nj][2] * 0.015625f, macc[mi][nj][3] * 0.015625f);
            *(float2*)&dst[(size_t)tok0 * NEXP + gcol] = v0;
            *(float2*)&dst[(size_t)tok8 * NEXP + gcol] = v1;
        }
    }
}

// ---------------------------------------------------------------------------
// routing core (verified semantics)
// ---------------------------------------------------------------------------
__device__ __forceinline__ void route_core(int token, const float* xs,
                                           const float* __restrict__ bias,
                                           void* __restrict__ out, int mode,
                                           int lane, bool check_margin) {
    const float* bp = bias + lane * 8;
    float4 b0 = *(const float4*)bp;
    float4 b1 = *(const float4*)(bp + 4);
    float bs[8] = {b0.x, b0.y, b0.z, b0.w, b1.x, b1.y, b1.z, b1.w};

    float s[8], sc[8];
#pragma unroll
    for (int jj = 0; jj < 8; jj++) {
        s[jj]  = 1.0f / (1.0f + expf(-xs[jj]));
        sc[jj] = s[jj] + bs[jj];
    }

    float m1 = -1e30f, m2 = -1e30f;
#pragma unroll
    for (int jj = 0; jj < 8; jj++) {
        float x = sc[jj];
        if (x > m1) { m2 = m1; m1 = x; }
        else if (x > m2) { m2 = x; }
    }
#pragma unroll
    for (int d = 1; d <= 2; d <<= 1) {
        float o1 = __shfl_xor_sync(0xffffffffu, m1, d);
        float o2 = __shfl_xor_sync(0xffffffffu, m2, d);
        float n2 = fmaxf(fminf(m1, o1), fmaxf(m2, o2));
        m1 = fmaxf(m1, o1);
        m2 = n2;
    }
    float gs = m1 + m2;

    float gsv[8];
#pragma unroll
    for (int gg = 0; gg < 8; gg++) gsv[gg] = __shfl_sync(0xffffffffu, gs, gg * 4);

    unsigned gsel = 0;
    float pick4 = 0.0f;
#pragma unroll
    for (int rr = 0; rr < TOPK_GRP; rr++) {
        float best = -1e30f; int bi = 0;
#pragma unroll
        for (int gg = 0; gg < 8; gg++) {
            float v = ((gsel >> gg) & 1u) ? -1e30f : gsv[gg];
            if (v > best) { best = v; bi = gg; }
        }
        gsel |= 1u << bi;
        if (rr == TOPK_GRP - 1) pick4 = best;
    }
    float best5 = -1e30f;
#pragma unroll
    for (int gg = 0; gg < 8; gg++) {
        float v = ((gsel >> gg) & 1u) ? -1e30f : gsv[gg];
        best5 = fmaxf(best5, v);
    }
    const float margin_g = pick4 - best5;

    const bool insel = (gsel >> (lane >> 2)) & 1u;
    float mv[8];
#pragma unroll
    for (int jj = 0; jj < 8; jj++) mv[jj] = insel ? sc[jj] : 0.0f;

    int   oi[8];
    float ow[8];
    float prevbv = 0.0f, mingap = 1e30f;
#pragma unroll
    for (int rr = 0; rr < TOPK; rr++) {
        float lb = mv[0]; int lj = 0;
#pragma unroll
        for (int jj = 1; jj < 8; jj++)
            if (mv[jj] > lb) { lb = mv[jj]; lj = jj; }
        float bv = lb;
        int   be = lane * 8 + lj;
#pragma unroll
        for (int off = 16; off >= 1; off >>= 1) {
            float ov = __shfl_xor_sync(0xffffffffu, bv, off);
            int   oe = __shfl_xor_sync(0xffffffffu, be, off);
            if (ov > bv || (ov == bv && oe < be)) { bv = ov; be = oe; }
        }
        oi[rr] = be;
        if (rr > 0) mingap = fminf(mingap, prevbv - bv);
        prevbv = bv;
        const int jj2 = be & 7;
        float sj = s[0];
#pragma unroll
        for (int jj = 1; jj < 8; jj++)
            if (jj2 == jj) sj = s[jj];
        ow[rr] = __shfl_sync(0xffffffffu, sj, be >> 3);
        if (lane == (be >> 3)) {
#pragma unroll
            for (int jj = 0; jj < 8; jj++)
                if (jj2 == jj) mv[jj] = -1e30f;
        }
    }

    bool flag = false;
    if (check_margin) {
        float lb = mv[0];
#pragma unroll
        for (int jj = 1; jj < 8; jj++) lb = fmaxf(lb, mv[jj]);
        float bv9 = lb;
#pragma unroll
        for (int off = 16; off >= 1; off >>= 1)
            bv9 = fmaxf(bv9, __shfl_xor_sync(0xffffffffu, bv9, off));
        mingap = fminf(mingap, prevbv - bv9);
        flag = (margin_g < TH_GRP) || (mingap < TH_EXP);
    }

    if (lane == 0) {
        if (flag) {
            int pos = atomicAdd(&g_cnt, 1);
            g_list[pos] = token;
        } else {
            float sum = 0.0f;
#pragma unroll
            for (int rr = 0; rr < TOPK; rr++) sum += ow[rr];
            const float den = sum + 1e-20f;
            if (mode == 0) {
                float* of = (float*)out;
#pragma unroll
                for (int rr = 0; rr < TOPK; rr++) {
                    of[(size_t)token * TOPK + rr] = (float)oi[rr];
                    of[(size_t)T_TOK * TOPK + (size_t)token * TOPK + rr] =
                        (ow[rr] / den) * 2.5f;
                }
            } else {
                int* op = (int*)out;
#pragma unroll
                for (int rr = 0; rr < TOPK; rr++) op[(size_t)token * TOPK + rr] = oi[rr];
            }
        }
    }
}

__global__ __launch_bounds__(256) void route_flag(const float* __restrict__ bias,
                                                  void* __restrict__ out, int mode) {
    const int warp = (blockIdx.x * blockDim.x + threadIdx.x) >> 5;
    const int lane = threadIdx.x & 31;
    if (warp >= T_TOK) return;

    const float* lg0 = g_part0 + (size_t)warp * NEXP + lane * 8;
    const float* lg1 = g_part1 + (size_t)warp * NEXP + lane * 8;
    const float* lg2 = g_part2 + (size_t)warp * NEXP + lane * 8;
    float4 x0 = *(const float4*)lg0;
    float4 x1 = *(const float4*)(lg0 + 4);
    float4 y0 = *(const float4*)lg1;
    float4 y1 = *(const float4*)(lg1 + 4);
    float4 z0 = *(const float4*)lg2;
    float4 z1 = *(const float4*)(lg2 + 4);
    float xs[8] = {x0.x + y0.x + z0.x, x0.y + y0.y + z0.y,
                   x0.z + y0.z + z0.z, x0.w + y0.w + z0.w,
                   x1.x + y1.x + z1.x, x1.y + y1.y + z1.y,
                   x1.z + y1.z + z1.z, x1.w + y1.w + z1.w};
    route_core(warp, xs, bias, out, mode, lane, true);
}

__global__ __launch_bounds__(256) void route_final(const float* __restrict__ bias,
                                                   void* __restrict__ out, int mode) {
    const int w = (blockIdx.x * blockDim.x + threadIdx.x) >> 5;
    const int lane = threadIdx.x & 31;
    if (w >= g_cnt) return;
    const int token = g_list[w];

    float xs[8] = {0, 0, 0, 0, 0, 0, 0, 0};
#pragma unroll
    for (int kq = 0; kq < KSPLIT; kq++) {
        const float* lg = g_rbuf[kq] + (size_t)token * NEXP + lane * 8;
        float4 a = *(const float4*)lg;
        float4 b = *(const float4*)(lg + 4);
        xs[0] += a.x; xs[1] += a.y; xs[2] += a.z; xs[3] += a.w;
        xs[4] += b.x; xs[5] += b.y; xs[6] += b.z; xs[7] += b.w;
    }
    route_core(token, xs, bias, out, mode, lane, false);
}

extern "C" void kernel_launch(void* const* d_in, const int* in_sizes, int n_in,
                              void* d_out, int out_size) {
    const float* hs   = (const float*)d_in[0];
    const float* w    = (const float*)d_in[1];
    const float* bias = (const float*)d_in[2];

    cudaFuncSetAttribute(gemm_hi, cudaFuncAttributeMaxDynamicSharedMemorySize, P_SM_TOTAL);
    cudaFuncSetAttribute(gemm_refine, cudaFuncAttributeMaxDynamicSharedMemorySize, R_SM_TOTAL);

    const int mode = (out_size >= 2 * T_TOK * TOPK) ? 0 : 1;

    w_convert<<<(NEXP * HDIM / 4) / 256, 256>>>(w);
    gemm_hi<<<NSM, THREADS, P_SM_TOTAL>>>(hs);
    route_flag<<<T_TOK / 8, 256>>>(bias, d_out, mode);
    gemm_refine<<<dim3(2, 128, KSPLIT), THREADS, R_SM_TOTAL>>>(hs);
    route_final<<<T_TOK / 8, 256>>>(bias, d_out, mode);
}